// round 15
// baseline (speedup 1.0000x reference)
#include <cuda_runtime.h>
#include <cuda_fp16.h>

#define N_NODES 100000
#define N_EDGES 1600000
#define F_IN    128
#define HID     64
#define NCLS    16
#define TPB     256
#define GRID    592           // 148 SMs x 4 blocks, all co-resident
#define GA      296           // prep group
#define GB      (GRID - GA)   // gemm1 group
#define NCHUNK  ((N_NODES + TPB - 1) / TPB)   // 391

typedef unsigned long long ull;

// ---------------- f32x2 helpers ----------------
__device__ __forceinline__ ull pack2(float x, float y) {
    ull r; asm("mov.b64 %0, {%1, %2};" : "=l"(r) : "f"(x), "f"(y)); return r;
}
__device__ __forceinline__ void unpack2(ull v, float& x, float& y) {
    asm("mov.b64 {%0, %1}, %2;" : "=f"(x), "=f"(y) : "l"(v));
}
__device__ __forceinline__ ull fma2(ull a, ull b, ull c) {
    ull d; asm("fma.rn.f32x2 %0, %1, %2, %3;" : "=l"(d) : "l"(a), "l"(b), "l"(c)); return d;
}
// L2-only load of a half2 (bypasses possibly-stale L1 for cross-phase rewrites)
__device__ __forceinline__ float2 ldcg_h2(const __half2* p) {
    unsigned u;
    asm volatile("ld.global.cg.u32 %0, [%1];" : "=r"(u) : "l"(p));
    __half2 h = *reinterpret_cast<__half2*>(&u);
    return __half22float2(h);
}

// ---------------- scratch ----------------
__device__ float g_dinv[N_NODES];
__device__ int   g_cnt[N_NODES];                 // ALWAYS zero between launches
__device__ int   g_px[N_NODES];
__device__ int   g_bsum[NCHUNK];
__device__ int   g_rowptr[N_NODES + 1];
__device__ int   g_fill[N_NODES];
__device__ __align__(16) int2 g_epk[N_EDGES];    // CSR: (src, norm-bits) by dst
__device__ __align__(16) __half2 g_xwh[(size_t)N_NODES * (HID / 2)]; // fp16 xw (layers 1,2)
__device__ __align__(16) __half2 g_hh [(size_t)N_NODES * (HID / 2)]; // fp16 relu(h)
__device__ __align__(16) float   g_xw [(size_t)N_NODES * NCLS];      // fp32 xw (layer 3)
__device__ unsigned g_bar[16];                   // monotonic ticket barriers

// grid barrier: monotonic counters, correct across graph replays (no reset)
__device__ __forceinline__ void grid_bar(int idx, unsigned nb) {
    __syncthreads();
    if (threadIdx.x == 0) {
        __threadfence();                          // release prior writes
        unsigned ticket = atomicAdd(&g_bar[idx], 1u);
        unsigned target = ticket - (ticket % nb) + nb;
        while (*(volatile unsigned*)&g_bar[idx] < target) __nanosleep(64);
        __threadfence();                          // acquire
    }
    __syncthreads();
}

// ---------------- GEMM C=64 phase (f32x2, fp16 out) ----------------
template<int K, bool FROM_H>
__device__ __forceinline__ void gemm64_phase(const float* __restrict__ X,
                                             const float* __restrict__ W,
                                             char* smem, int gb, int gs) {
    ull*    Ws2 = (ull*)smem;                           // K*32*8 bytes
    float4* xs4 = (float4*)(smem + (size_t)K * 32 * 8); // 8*4*(K/4)*16 bytes
    const ull* Wv = (const ull*)W;
    for (int i = threadIdx.x; i < K * 32; i += TPB) Ws2[i] = Wv[i];
    __syncthreads();

    const int warp = threadIdx.x >> 5;
    const int lane = threadIdx.x & 31;

    for (int base = (gb * 8 + warp) * 4; base < N_NODES; base += gs * 32) {
        #pragma unroll
        for (int n = 0; n < 4; n++) {
            int node = base + n;
            if (node < N_NODES) {
                float* xrow = (float*)&xs4[(warp * 4 + n) * (K / 4)];
                if (FROM_H) {
                    float2 v = ldcg_h2(&g_hh[(size_t)node * (HID / 2) + lane]);
                    xrow[2 * lane]     = v.x;     // relu pre-applied at pull
                    xrow[2 * lane + 1] = v.y;
                } else {
                    for (int k = lane; k < K; k += 32)
                        xrow[k] = X[(size_t)node * K + k];
                }
            }
        }
        __syncwarp();

        ull acc[4] = {0ull, 0ull, 0ull, 0ull};
        #pragma unroll 4
        for (int k4 = 0; k4 < K / 4; k4++) {
            float4 xv[4];
            #pragma unroll
            for (int n = 0; n < 4; n++) xv[n] = xs4[(warp * 4 + n) * (K / 4) + k4];
            #pragma unroll
            for (int kk = 0; kk < 4; kk++) {
                ull w = Ws2[(k4 * 4 + kk) * 32 + lane];
                float x0 = (kk == 0) ? xv[0].x : (kk == 1) ? xv[0].y : (kk == 2) ? xv[0].z : xv[0].w;
                float x1 = (kk == 0) ? xv[1].x : (kk == 1) ? xv[1].y : (kk == 2) ? xv[1].z : xv[1].w;
                float x2 = (kk == 0) ? xv[2].x : (kk == 1) ? xv[2].y : (kk == 2) ? xv[2].z : xv[2].w;
                float x3 = (kk == 0) ? xv[3].x : (kk == 1) ? xv[3].y : (kk == 2) ? xv[3].z : xv[3].w;
                acc[0] = fma2(w, pack2(x0, x0), acc[0]);
                acc[1] = fma2(w, pack2(x1, x1), acc[1]);
                acc[2] = fma2(w, pack2(x2, x2), acc[2]);
                acc[3] = fma2(w, pack2(x3, x3), acc[3]);
            }
        }

        #pragma unroll
        for (int n = 0; n < 4; n++) {
            int node = base + n;
            if (node < N_NODES) {
                float lo, hi; unpack2(acc[n], lo, hi);
                g_xwh[(size_t)node * (HID / 2) + lane] = __floats2half2_rn(lo, hi);
            }
        }
        __syncwarp();
    }
}

// ---------------- GEMM C=16 phase (layer 3, fp32 out) ----------------
__device__ __forceinline__ void gemm16_phase(const float* __restrict__ W, char* smem) {
    float* Ws = (float*)smem;                 // 4KB
    float* xs = (float*)(smem + HID * NCLS * 4);  // 8*4*HID floats = 8KB
    for (int i = threadIdx.x; i < HID * NCLS; i += TPB) Ws[i] = W[i];
    __syncthreads();

    const int warp = threadIdx.x >> 5;
    const int lane = threadIdx.x & 31;
    const int col  = lane & 15;
    const int half = lane >> 4;

    for (int base = ((int)blockIdx.x * 8 + warp) * 4; base < N_NODES;
         base += GRID * 32) {
        #pragma unroll
        for (int n = 0; n < 4; n++) {
            int node = base + n;
            if (node < N_NODES) {
                float2 v = ldcg_h2(&g_hh[(size_t)node * (HID / 2) + lane]);
                float* xrow = xs + (warp * 4 + n) * HID;
                xrow[2 * lane]     = v.x;
                xrow[2 * lane + 1] = v.y;
            }
        }
        __syncwarp();

        float acc[4] = {0, 0, 0, 0};
        #pragma unroll 4
        for (int k = half * (HID / 2); k < (half + 1) * (HID / 2); k++) {
            float w = Ws[k * NCLS + col];
            #pragma unroll
            for (int n = 0; n < 4; n++)
                acc[n] = fmaf(xs[(warp * 4 + n) * HID + k], w, acc[n]);
        }
        #pragma unroll
        for (int n = 0; n < 4; n++) {
            acc[n] += __shfl_xor_sync(0xFFFFFFFFu, acc[n], 16);
            int node = base + n;
            if (node < N_NODES && half == 0)
                g_xw[(size_t)node * NCLS + col] = acc[n];
        }
        __syncwarp();
    }
}

// ---------------- pull phase (2 nodes/warp, interleaved chains, ldcg gathers) ----------------
__device__ __forceinline__ ull edge_fma2h(ull acc, int2 p, int lane) {
    float2 v = ldcg_h2(&g_xwh[(size_t)p.x * (HID / 2) + lane]);
    float w = __int_as_float(p.y);
    return fma2(pack2(v.x, v.y), pack2(w, w), acc);
}
__device__ __forceinline__ ull pull_init(const float* __restrict__ b, int node, int lane) {
    float2 bb = ((const float2*)b)[lane];
    float di = g_dinv[node], di2 = di * di;
    float2 xr = ldcg_h2(&g_xwh[(size_t)node * (HID / 2) + lane]);
    return pack2(fmaf(xr.x, di2, bb.x), fmaf(xr.y, di2, bb.y));
}

__device__ __forceinline__ void pull64_phase(const float* __restrict__ b) {
    int warp = threadIdx.x >> 5, lane = threadIdx.x & 31;
    for (int gw = (int)blockIdx.x * 8 + warp; gw * 2 < N_NODES; gw += GRID * 8) {
        int n0 = gw * 2, n1 = n0 + 1;
        bool has1 = (n1 < N_NODES);

        int e0 = g_rowptr[n0], end0 = g_rowptr[n0 + 1];
        int e1 = 0, end1 = 0;
        if (has1) { e1 = end0; end1 = g_rowptr[n1 + 1]; }

        ull a0 = pull_init(b, n0, lane);
        ull a1 = has1 ? pull_init(b, n1, lane) : 0ull;

        while (e0 + 3 < end0 && e1 + 3 < end1) {
            int2 p00 = g_epk[e0], p01 = g_epk[e0 + 1], p02 = g_epk[e0 + 2], p03 = g_epk[e0 + 3];
            int2 p10 = g_epk[e1], p11 = g_epk[e1 + 1], p12 = g_epk[e1 + 2], p13 = g_epk[e1 + 3];
            a0 = edge_fma2h(a0, p00, lane);
            a1 = edge_fma2h(a1, p10, lane);
            a0 = edge_fma2h(a0, p01, lane);
            a1 = edge_fma2h(a1, p11, lane);
            a0 = edge_fma2h(a0, p02, lane);
            a1 = edge_fma2h(a1, p12, lane);
            a0 = edge_fma2h(a0, p03, lane);
            a1 = edge_fma2h(a1, p13, lane);
            e0 += 4; e1 += 4;
        }
        for (; e0 + 3 < end0; e0 += 4) {
            int2 p0 = g_epk[e0], p1 = g_epk[e0 + 1], p2 = g_epk[e0 + 2], p3 = g_epk[e0 + 3];
            a0 = edge_fma2h(a0, p0, lane);
            a0 = edge_fma2h(a0, p1, lane);
            a0 = edge_fma2h(a0, p2, lane);
            a0 = edge_fma2h(a0, p3, lane);
        }
        for (; e0 < end0; e0++) a0 = edge_fma2h(a0, g_epk[e0], lane);
        for (; e1 + 3 < end1; e1 += 4) {
            int2 p0 = g_epk[e1], p1 = g_epk[e1 + 1], p2 = g_epk[e1 + 2], p3 = g_epk[e1 + 3];
            a1 = edge_fma2h(a1, p0, lane);
            a1 = edge_fma2h(a1, p1, lane);
            a1 = edge_fma2h(a1, p2, lane);
            a1 = edge_fma2h(a1, p3, lane);
        }
        for (; e1 < end1; e1++) a1 = edge_fma2h(a1, g_epk[e1], lane);

        float lo, hi; unpack2(a0, lo, hi);
        g_hh[(size_t)n0 * (HID / 2) + lane] =
            __floats2half2_rn(fmaxf(lo, 0.0f), fmaxf(hi, 0.0f));   // relu fused
        if (has1) {
            unpack2(a1, lo, hi);
            g_hh[(size_t)n1 * (HID / 2) + lane] =
                __floats2half2_rn(fmaxf(lo, 0.0f), fmaxf(hi, 0.0f));
        }
    }
}

__device__ __forceinline__ void pull16_phase(const float* __restrict__ b,
                                             float* __restrict__ out) {
    int warp = threadIdx.x >> 5, lane = threadIdx.x & 31;
    int col = lane & 15, eh = lane >> 4;
    for (int node = (int)blockIdx.x * 8 + warp; node < N_NODES; node += GRID * 8) {
        float di = g_dinv[node];
        float a = 0.0f;
        if (eh == 0) a = fmaf(g_xw[(size_t)node * NCLS + col], di * di, b[col]);

        int start = g_rowptr[node], end = g_rowptr[node + 1];
        for (int e = start + eh; e < end; e += 2) {
            int2 p = g_epk[e];
            a = fmaf(g_xw[(size_t)p.x * NCLS + col], __int_as_float(p.y), a);
        }
        a += __shfl_xor_sync(0xFFFFFFFFu, a, 16);
        if (eh == 0) out[(size_t)node * NCLS + col] = a;
    }
}

// ---------------- the persistent mega-kernel ----------------
__global__ void __launch_bounds__(TPB, 4) gcn_mega(
    const float* __restrict__ x, const void* __restrict__ ei,
    const float* __restrict__ W1, const float* __restrict__ b1,
    const float* __restrict__ W2, const float* __restrict__ b2,
    const float* __restrict__ W3, const float* __restrict__ b3,
    float* __restrict__ out)
{
    __shared__ __align__(16) char smem[49152];   // union across phases (48KB)
    const int tid = threadIdx.x;
    const int bid = blockIdx.x;

    // dtype detect (each block, 16 cached reads)
    int is64;
    {
        const long long* e64 = (const long long*)ei;
        int ok = 1;
        #pragma unroll
        for (int k = 0; k < 16; k++) {
            long long v = e64[k];
            if (v < 0 || v >= N_NODES) ok = 0;
        }
        is64 = ok;
    }

    if (bid < GA) {
        // ======== prep group: P0 histogram ========
        for (int t = bid * TPB + tid; 2 * t < N_EDGES; t += GA * TPB) {
            int d0, d1;
            if (is64) {
                const longlong2* dv = (const longlong2*)((const long long*)ei + N_EDGES);
                longlong2 dd = dv[t]; d0 = (int)dd.x; d1 = (int)dd.y;
            } else {
                const int2* dv = (const int2*)((const int*)ei + N_EDGES);
                int2 dd = dv[t]; d0 = dd.x; d1 = dd.y;
            }
            if ((unsigned)d0 >= N_NODES) d0 = 0;
            if ((unsigned)d1 >= N_NODES) d1 = 0;
            atomicAdd(&g_cnt[d0], 1);
            atomicAdd(&g_cnt[d1], 1);
        }
        grid_bar(0, GA);
        // ======== P1: 256-wide block scans ========
        {
            int* s = (int*)smem;
            for (int c = bid; c < NCHUNK; c += GA) {
                int idx = c * TPB + tid;
                int v = (idx < N_NODES) ? g_cnt[idx] : 0;
                s[tid] = v;
                __syncthreads();
                for (int off = 1; off < TPB; off <<= 1) {
                    int add = (tid >= off) ? s[tid - off] : 0;
                    __syncthreads();
                    s[tid] += add;
                    __syncthreads();
                }
                int incl = s[tid];
                if (idx < N_NODES) g_px[idx] = incl - v;
                if (tid == TPB - 1) g_bsum[c] = incl;
                __syncthreads();
            }
        }
        grid_bar(1, GA);
        // ======== P2: rowptr/fill/dinv + cnt self-clean ========
        {
            int* s_ofs = (int*)smem;
            for (int w = bid; w < NCHUNK; w += GA) {
                if (tid < 32) {
                    int acc = 0;
                    for (int i = tid; i < w; i += 32) acc += g_bsum[i];
                    #pragma unroll
                    for (int off = 16; off > 0; off >>= 1)
                        acc += __shfl_xor_sync(0xFFFFFFFFu, acc, off);
                    if (tid == 0) s_ofs[0] = acc;
                }
                __syncthreads();
                int idx = w * TPB + tid;
                if (idx < N_NODES) {
                    int base = g_px[idx] + s_ofs[0];
                    g_rowptr[idx] = base;
                    g_fill[idx]   = base;
                    g_dinv[idx]   = rsqrtf(1.0f + (float)g_cnt[idx]);
                    g_cnt[idx]    = 0;
                }
                if (idx == 0) g_rowptr[N_NODES] = N_EDGES;
                __syncthreads();
            }
        }
        grid_bar(2, GA);
        // ======== P3: scatter into CSR ========
        for (int t = bid * TPB + tid; 2 * t < N_EDGES; t += GA * TPB) {
            int s0, s1, d0, d1;
            if (is64) {
                const longlong2* sv = (const longlong2*)((const long long*)ei);
                const longlong2* dv = (const longlong2*)((const long long*)ei + N_EDGES);
                longlong2 ss = sv[t], dd = dv[t];
                s0 = (int)ss.x; s1 = (int)ss.y; d0 = (int)dd.x; d1 = (int)dd.y;
            } else {
                const int2* sv = (const int2*)((const int*)ei);
                const int2* dv = (const int2*)((const int*)ei + N_EDGES);
                int2 ss = sv[t], dd = dv[t];
                s0 = ss.x; s1 = ss.y; d0 = dd.x; d1 = dd.y;
            }
            if ((unsigned)s0 >= N_NODES) s0 = 0;
            if ((unsigned)s1 >= N_NODES) s1 = 0;
            if ((unsigned)d0 >= N_NODES) d0 = 0;
            if ((unsigned)d1 >= N_NODES) d1 = 0;
            int p0 = atomicAdd(&g_fill[d0], 1);
            g_epk[p0] = make_int2(s0, __float_as_int(g_dinv[s0] * g_dinv[d0]));
            int p1 = atomicAdd(&g_fill[d1], 1);
            g_epk[p1] = make_int2(s1, __float_as_int(g_dinv[s1] * g_dinv[d1]));
        }
    } else {
        // ======== gemm group: layer-1 GEMM concurrent with prep ========
        gemm64_phase<F_IN, false>(x, W1, smem, bid - GA, GB);
    }

    grid_bar(3, GRID);                      // join: CSR + xw1 both ready
    pull64_phase(b1);                       // P4: h1 = agg(xw1) -> g_hh
    grid_bar(4, GRID);
    gemm64_phase<HID, true>(nullptr, W2, smem, bid, GRID);  // P5: xw2
    grid_bar(5, GRID);
    pull64_phase(b2);                       // P6: h2 -> g_hh
    grid_bar(6, GRID);
    gemm16_phase(W3, smem);                 // P7: xw3 -> g_xw
    grid_bar(7, GRID);
    pull16_phase(b3, out);                  // P8: final aggregation
}

// ---------------- launch ----------------
extern "C" void kernel_launch(void* const* d_in, const int* in_sizes, int n_in,
                              void* d_out, int out_size) {
    const float* x  = (const float*)d_in[0];
    const void*  ei = d_in[1];
    const float* W1 = (const float*)d_in[2];
    const float* b1 = (const float*)d_in[3];
    const float* W2 = (const float*)d_in[4];
    const float* b2 = (const float*)d_in[5];
    const float* W3 = (const float*)d_in[6];
    const float* b3 = (const float*)d_in[7];
    float* out = (float*)d_out;

    gcn_mega<<<GRID, TPB>>>(x, ei, W1, b1, W2, b2, W3, b3, out);
}